// round 1
// baseline (speedup 1.0000x reference)
#include <cuda_runtime.h>
#include <math.h>

#define T_DIM 128
#define B_DIM 64
#define C_DIM 768
#define M_DIM (T_DIM * B_DIM)   // 8192
#define K_DW  31
#define EPSF  1e-5f

// ---------------- scratch (static device allocations; no cudaMalloc) ----------------
__device__ float g_H  [M_DIM * C_DIM];       // layernorm out
__device__ float g_Y1 [M_DIM * C_DIM];       // pw1 + bn1
__device__ float g_S1 [M_DIM * C_DIM];       // lif1 spikes
__device__ float g_D  [M_DIM * C_DIM];       // depthwise out
__device__ float g_S2 [M_DIM * C_DIM];       // lif2 spikes
__device__ float g_Y2 [M_DIM * 2 * C_DIM];   // pw2 + bn3 (out | gate)
__device__ float g_Sg [M_DIM * C_DIM];       // lif(gate) spikes
__device__ float g_Y3 [M_DIM * C_DIM];       // gsu + gsu_bn
__device__ float g_Sg2[M_DIM * C_DIM];       // lif(gsu) spikes

// ---------------- block reduction helper ----------------
__inline__ __device__ float block_reduce_sum(float val, float* shmem) {
    int tid = threadIdx.x;
    #pragma unroll
    for (int o = 16; o > 0; o >>= 1) val += __shfl_xor_sync(0xffffffffu, val, o);
    if ((tid & 31) == 0) shmem[tid >> 5] = val;
    __syncthreads();
    float r = 0.0f;
    if (tid < 8) r = shmem[tid];
    if (tid < 32) {
        #pragma unroll
        for (int o = 4; o > 0; o >>= 1) r += __shfl_xor_sync(0xffffffffu, r, o);
    }
    if (tid == 0) shmem[0] = r;
    __syncthreads();
    r = shmem[0];
    __syncthreads();   // allow shmem reuse by caller
    return r;
}

// ---------------- layernorm over C (one block per row) ----------------
__global__ void __launch_bounds__(256) ln_kernel(
    const float* __restrict__ x, const float* __restrict__ gam,
    const float* __restrict__ bet, float* __restrict__ out)
{
    __shared__ float red[32];
    int row = blockIdx.x;
    const float* xr = x + (size_t)row * C_DIM;
    float* orow = out + (size_t)row * C_DIM;
    int tid = threadIdx.x;

    float lx[3];
    float s = 0.0f;
    #pragma unroll
    for (int i = 0; i < 3; i++) { lx[i] = xr[tid + i * 256]; s += lx[i]; }
    float mean = block_reduce_sum(s, red) * (1.0f / C_DIM);

    float s2 = 0.0f;
    #pragma unroll
    for (int i = 0; i < 3; i++) { float d = lx[i] - mean; s2 += d * d; }
    float var = block_reduce_sum(s2, red) * (1.0f / C_DIM);
    float rstd = 1.0f / sqrtf(var + EPSF);

    #pragma unroll
    for (int i = 0; i < 3; i++) {
        int c = tid + i * 256;
        orow[c] = (lx[i] - mean) * rstd * gam[c] + bet[c];
    }
}

// ---------------- fp32 GEMM: Out[m,n] = bn( sum_k A[m,k]*W[n,k] + bias[n] ) -------
// A: [M,K] row-major, W: [N,K] row-major. 64x64 tile, BK=16, 256 thr, 4x4 microtile.
#define BM 64
#define BN 64
#define BK 16
__global__ void __launch_bounds__(256) gemm_bias_bn(
    const float* __restrict__ A, const float* __restrict__ W,
    const float* __restrict__ bias, const float* __restrict__ bnp,
    float* __restrict__ Out, int M, int N, int K)
{
    __shared__ float As[BK][BM + 4];
    __shared__ float Bs[BK][BN + 4];

    int tid = threadIdx.x;
    int bn0 = blockIdx.x * BN;
    int bm0 = blockIdx.y * BM;
    int tx = tid & 15;        // n direction
    int ty = tid >> 4;        // m direction

    float acc[4][4] = {};

    int la_r  = tid >> 2;          // 0..63  (row within tile)
    int la_k4 = (tid & 3) * 4;     // 0,4,8,12
    const float* Ap = A + (size_t)(bm0 + la_r) * K + la_k4;
    const float* Wp = W + (size_t)(bn0 + la_r) * K + la_k4;

    for (int k0 = 0; k0 < K; k0 += BK) {
        float4 av = *(const float4*)(Ap + k0);
        float4 wv = *(const float4*)(Wp + k0);
        __syncthreads();
        As[la_k4 + 0][la_r] = av.x; As[la_k4 + 1][la_r] = av.y;
        As[la_k4 + 2][la_r] = av.z; As[la_k4 + 3][la_r] = av.w;
        Bs[la_k4 + 0][la_r] = wv.x; Bs[la_k4 + 1][la_r] = wv.y;
        Bs[la_k4 + 2][la_r] = wv.z; Bs[la_k4 + 3][la_r] = wv.w;
        __syncthreads();
        #pragma unroll
        for (int kk = 0; kk < BK; kk++) {
            float4 a = *(const float4*)&As[kk][ty * 4];
            float4 b = *(const float4*)&Bs[kk][tx * 4];
            acc[0][0] += a.x * b.x; acc[0][1] += a.x * b.y; acc[0][2] += a.x * b.z; acc[0][3] += a.x * b.w;
            acc[1][0] += a.y * b.x; acc[1][1] += a.y * b.y; acc[1][2] += a.y * b.z; acc[1][3] += a.y * b.w;
            acc[2][0] += a.z * b.x; acc[2][1] += a.z * b.y; acc[2][2] += a.z * b.z; acc[2][3] += a.z * b.w;
            acc[3][0] += a.w * b.x; acc[3][1] += a.w * b.y; acc[3][2] += a.w * b.z; acc[3][3] += a.w * b.w;
        }
    }

    // epilogue: bias + (optional) BN affine
    int m0 = bm0 + ty * 4;
    int n0 = bn0 + tx * 4;
    #pragma unroll
    for (int j = 0; j < 4; j++) {
        int nn = n0 + j;
        float sc = 1.0f, sh = 0.0f;
        if (bnp) {
            float g = bnp[nn], be = bnp[N + nn], mm = bnp[2 * N + nn], vv = bnp[3 * N + nn];
            sc = g / sqrtf(vv + EPSF);
            sh = be - mm * sc;
        }
        float bs = bias[nn];
        #pragma unroll
        for (int i = 0; i < 4; i++) {
            Out[(size_t)(m0 + i) * N + nn] = (acc[i][j] + bs) * sc + sh;
        }
    }
}

// ---------------- LIF scan (optionally fused BN affine and elementwise multiply) --
// v_t = 0.5*v_{t-1} + x_t ; s = (v >= 1); v <- 0 if s
__global__ void __launch_bounds__(256) lif_kernel(
    const float* __restrict__ X, int ldx,
    const float* __restrict__ Mul, int ldm,
    const float* __restrict__ bnp,
    float* __restrict__ S)
{
    int j = blockIdx.x * blockDim.x + threadIdx.x;
    if (j >= B_DIM * C_DIM) return;
    int b = j / C_DIM, c = j % C_DIM;

    float sc = 1.0f, sh = 0.0f;
    if (bnp) {
        float g = bnp[c], be = bnp[C_DIM + c], mm = bnp[2 * C_DIM + c], vv = bnp[3 * C_DIM + c];
        sc = g / sqrtf(vv + EPSF);
        sh = be - mm * sc;
    }

    const float* xp = X + (size_t)b * ldx + c;
    const float* mp = Mul ? (Mul + (size_t)b * ldm + c) : nullptr;
    float* sp = S + (size_t)j;
    size_t stx = (size_t)B_DIM * ldx;
    size_t stm = (size_t)B_DIM * ldm;
    size_t sts = (size_t)B_DIM * C_DIM;

    float vm = 0.0f;
    for (int t = 0; t < T_DIM; t++) {
        float xv = xp[(size_t)t * stx];
        if (mp) xv *= mp[(size_t)t * stm];
        xv = xv * sc + sh;
        vm = vm * 0.5f + xv;
        float s = (vm >= 1.0f) ? 1.0f : 0.0f;
        vm = (s > 0.0f) ? 0.0f : vm;
        sp[(size_t)t * sts] = s;
    }
}

// ---------------- depthwise conv over time (K=31, SAME zero pad) ----------------
__global__ void __launch_bounds__(256) dw_kernel(
    const float* __restrict__ S1, const float* __restrict__ w,
    const float* __restrict__ bvec, float* __restrict__ Dout)
{
    __shared__ float sx[T_DIM][64];
    int b  = blockIdx.x;
    int c0 = blockIdx.y * 64;
    int tid = threadIdx.x;

    for (int i = tid; i < T_DIM * 64; i += 256) {
        int t = i >> 6, ci = i & 63;
        sx[t][ci] = S1[((size_t)t * B_DIM + b) * C_DIM + c0 + ci];
    }
    __syncthreads();

    int ci = tid & 63;
    int tg = tid >> 6;      // 4 time-groups of 32 steps
    int c  = c0 + ci;

    float wr[K_DW];
    #pragma unroll
    for (int k = 0; k < K_DW; k++) wr[k] = w[c * K_DW + k];
    float bb = bvec[c];

    for (int t = tg * 32; t < tg * 32 + 32; t++) {
        float acc = bb;
        #pragma unroll
        for (int k = 0; k < K_DW; k++) {
            int tt = t + k - 15;
            if (tt >= 0 && tt < T_DIM) acc += sx[tt][ci] * wr[k];
        }
        Dout[((size_t)t * B_DIM + b) * C_DIM + c] = acc;
    }
}

// ---------------- launch ----------------
extern "C" void kernel_launch(void* const* d_in, const int* in_sizes, int n_in,
                              void* d_out, int out_size)
{
    const float* x        = (const float*)d_in[0];
    const float* ln_g     = (const float*)d_in[1];
    const float* ln_b     = (const float*)d_in[2];
    const float* pw1_w    = (const float*)d_in[3];
    const float* pw1_b    = (const float*)d_in[4];
    const float* bn1_p    = (const float*)d_in[5];
    const float* dw_w     = (const float*)d_in[6];
    const float* dw_b     = (const float*)d_in[7];
    const float* bn2_p    = (const float*)d_in[8];
    const float* pw2_w    = (const float*)d_in[9];
    const float* pw2_b    = (const float*)d_in[10];
    const float* bn3_p    = (const float*)d_in[11];
    const float* gsu_w    = (const float*)d_in[12];
    const float* gsu_b    = (const float*)d_in[13];
    const float* gsu_bn_p = (const float*)d_in[14];

    float *H, *Y1, *S1, *D, *S2, *Y2, *Sg, *Y3, *Sg2;
    cudaGetSymbolAddress((void**)&H,   g_H);
    cudaGetSymbolAddress((void**)&Y1,  g_Y1);
    cudaGetSymbolAddress((void**)&S1,  g_S1);
    cudaGetSymbolAddress((void**)&D,   g_D);
    cudaGetSymbolAddress((void**)&S2,  g_S2);
    cudaGetSymbolAddress((void**)&Y2,  g_Y2);
    cudaGetSymbolAddress((void**)&Sg,  g_Sg);
    cudaGetSymbolAddress((void**)&Y3,  g_Y3);
    cudaGetSymbolAddress((void**)&Sg2, g_Sg2);

    const int lif_blocks = (B_DIM * C_DIM + 255) / 256;   // 192

    // 1) LayerNorm
    ln_kernel<<<M_DIM, 256>>>(x, ln_g, ln_b, H);

    // 2) pw1 + bias + bn1
    gemm_bias_bn<<<dim3(C_DIM / BN, M_DIM / BM), 256>>>(
        H, pw1_w, pw1_b, bn1_p, Y1, M_DIM, C_DIM, C_DIM);

    // 3) LIF -> S1
    lif_kernel<<<lif_blocks, 256>>>(Y1, C_DIM, nullptr, 0, nullptr, S1);

    // 4) depthwise over time
    dw_kernel<<<dim3(B_DIM, C_DIM / 64), 256>>>(S1, dw_w, dw_b, D);

    // 5) BN2 + LIF -> S2
    lif_kernel<<<lif_blocks, 256>>>(D, C_DIM, nullptr, 0, bn2_p, S2);

    // 6) pw2 + bias + bn3 -> [out | gate]
    gemm_bias_bn<<<dim3(2 * C_DIM / BN, M_DIM / BM), 256>>>(
        S2, pw2_w, pw2_b, bn3_p, Y2, M_DIM, 2 * C_DIM, C_DIM);

    // 7) LIF(gate half) -> Sg
    lif_kernel<<<lif_blocks, 256>>>(Y2 + C_DIM, 2 * C_DIM, nullptr, 0, nullptr, Sg);

    // 8) gsu GEMM + bias + gsu_bn
    gemm_bias_bn<<<dim3(C_DIM / BN, M_DIM / BM), 256>>>(
        Sg, gsu_w, gsu_b, gsu_bn_p, Y3, M_DIM, C_DIM, C_DIM);

    // 9) LIF -> Sg2
    lif_kernel<<<lif_blocks, 256>>>(Y3, C_DIM, nullptr, 0, nullptr, Sg2);

    // 10) final LIF on out*Sg2 -> d_out
    lif_kernel<<<lif_blocks, 256>>>(Y2, 2 * C_DIM, Sg2, C_DIM, nullptr, (float*)d_out);
}

// round 2
// speedup vs baseline: 1.2433x; 1.2433x over previous
#include <cuda_runtime.h>
#include <math.h>

#define T_DIM 128
#define B_DIM 64
#define C_DIM 768
#define M_DIM (T_DIM * B_DIM)   // 8192
#define K_DW  31
#define EPSF  1e-5f

typedef unsigned long long ull;

// ---------------- scratch (static device allocations; no cudaMalloc) ----------------
__device__ float g_H  [M_DIM * C_DIM];       // layernorm out
__device__ float g_Y1 [M_DIM * C_DIM];       // pw1 + bn1
__device__ float g_S1 [M_DIM * C_DIM];       // lif1 spikes
__device__ float g_D  [M_DIM * C_DIM];       // depthwise out
__device__ float g_S2 [M_DIM * C_DIM];       // lif2 spikes
__device__ float g_Y2 [M_DIM * 2 * C_DIM];   // pw2 + bn3 (out | gate)
__device__ float g_Sg [M_DIM * C_DIM];       // lif(gate) spikes
__device__ float g_Y3 [M_DIM * C_DIM];       // gsu + gsu_bn
__device__ float g_Sg2[M_DIM * C_DIM];       // lif(gsu) spikes

// ---------------- packed f32x2 helpers (Blackwell FFMA2 path) ----------------
__device__ __forceinline__ ull dup2(float v) {
    ull r; asm("mov.b64 %0, {%1, %1};" : "=l"(r) : "f"(v)); return r;
}
__device__ __forceinline__ ull pack2(float lo, float hi) {
    ull r; asm("mov.b64 %0, {%1, %2};" : "=l"(r) : "f"(lo), "f"(hi)); return r;
}
__device__ __forceinline__ void fma2(ull &d, ull a, ull b) {
    asm("fma.rn.f32x2 %0, %1, %2, %0;" : "+l"(d) : "l"(a), "l"(b));
}
__device__ __forceinline__ float2 unpack2(ull v) {
    float2 r; asm("mov.b64 {%0, %1}, %2;" : "=f"(r.x), "=f"(r.y) : "l"(v)); return r;
}

// ---------------- block reduction helper ----------------
__inline__ __device__ float block_reduce_sum(float val, float* shmem) {
    int tid = threadIdx.x;
    #pragma unroll
    for (int o = 16; o > 0; o >>= 1) val += __shfl_xor_sync(0xffffffffu, val, o);
    if ((tid & 31) == 0) shmem[tid >> 5] = val;
    __syncthreads();
    float r = 0.0f;
    if (tid < 8) r = shmem[tid];
    if (tid < 32) {
        #pragma unroll
        for (int o = 4; o > 0; o >>= 1) r += __shfl_xor_sync(0xffffffffu, r, o);
    }
    if (tid == 0) shmem[0] = r;
    __syncthreads();
    r = shmem[0];
    __syncthreads();
    return r;
}

// ---------------- layernorm over C (one block per row) ----------------
__global__ void __launch_bounds__(256) ln_kernel(
    const float* __restrict__ x, const float* __restrict__ gam,
    const float* __restrict__ bet, float* __restrict__ out)
{
    __shared__ float red[32];
    int row = blockIdx.x;
    const float* xr = x + (size_t)row * C_DIM;
    float* orow = out + (size_t)row * C_DIM;
    int tid = threadIdx.x;

    float lx[3];
    float s = 0.0f;
    #pragma unroll
    for (int i = 0; i < 3; i++) { lx[i] = xr[tid + i * 256]; s += lx[i]; }
    float mean = block_reduce_sum(s, red) * (1.0f / C_DIM);

    float s2 = 0.0f;
    #pragma unroll
    for (int i = 0; i < 3; i++) { float d = lx[i] - mean; s2 += d * d; }
    float var = block_reduce_sum(s2, red) * (1.0f / C_DIM);
    float rstd = 1.0f / sqrtf(var + EPSF);

    #pragma unroll
    for (int i = 0; i < 3; i++) {
        int c = tid + i * 256;
        orow[c] = (lx[i] - mean) * rstd * gam[c] + bet[c];
    }
}

// ---------------- fp32 GEMM via packed FFMA2 -------------------------------
// Out[m,n] = bn( sum_k A[m,k]*W[n,k] + bias[n] )
// A: [M,K] row-major, W: [N,K] row-major. 128x128 tile, BK=16, 256 thr,
// 8x8 microtile split as two 4x4 quadrants (m: ty*4 / +64, n: tx*4 / +64).
// Accumulators packed as f32x2 n-pairs -> fma.rn.f32x2 (full-rate fp32 path).
#define BM 128
#define BN 128
#define BK 16
__global__ void __launch_bounds__(256) gemm_bias_bn(
    const float* __restrict__ A, const float* __restrict__ W,
    const float* __restrict__ bias, const float* __restrict__ bnp,
    float* __restrict__ Out, int M, int N, int K)
{
    __shared__ float As[BK][BM + 4];
    __shared__ float Bs[BK][BN + 4];

    int tid = threadIdx.x;
    int bn0 = blockIdx.x * BN;
    int bm0 = blockIdx.y * BM;
    int tx = tid & 15;        // n direction
    int ty = tid >> 4;        // m direction

    // global-load mapping: 256 threads cover 128 rows x 2 k-halves
    int lr = tid & 127;            // row within tile
    int lk = (tid >> 7) * 8;       // 0 or 8
    const float* Ap = A + (size_t)(bm0 + lr) * K + lk;
    const float* Wp = W + (size_t)(bn0 + lr) * K + lk;

    ull acc[8][4];
    #pragma unroll
    for (int i = 0; i < 8; i++)
        #pragma unroll
        for (int j = 0; j < 4; j++) acc[i][j] = 0ull;

    // register prefetch for step 0
    float4 pa0 = *(const float4*)(Ap);
    float4 pa1 = *(const float4*)(Ap + 4);
    float4 pb0 = *(const float4*)(Wp);
    float4 pb1 = *(const float4*)(Wp + 4);

    for (int k0 = 0; k0 < K; k0 += BK) {
        __syncthreads();
        As[lk + 0][lr] = pa0.x; As[lk + 1][lr] = pa0.y;
        As[lk + 2][lr] = pa0.z; As[lk + 3][lr] = pa0.w;
        As[lk + 4][lr] = pa1.x; As[lk + 5][lr] = pa1.y;
        As[lk + 6][lr] = pa1.z; As[lk + 7][lr] = pa1.w;
        Bs[lk + 0][lr] = pb0.x; Bs[lk + 1][lr] = pb0.y;
        Bs[lk + 2][lr] = pb0.z; Bs[lk + 3][lr] = pb0.w;
        Bs[lk + 4][lr] = pb1.x; Bs[lk + 5][lr] = pb1.y;
        Bs[lk + 6][lr] = pb1.z; Bs[lk + 7][lr] = pb1.w;
        __syncthreads();

        if (k0 + BK < K) {
            pa0 = *(const float4*)(Ap + k0 + BK);
            pa1 = *(const float4*)(Ap + k0 + BK + 4);
            pb0 = *(const float4*)(Wp + k0 + BK);
            pb1 = *(const float4*)(Wp + k0 + BK + 4);
        }

        #pragma unroll
        for (int kk = 0; kk < BK; kk++) {
            float4 av0 = *(const float4*)&As[kk][ty * 4];
            float4 av1 = *(const float4*)&As[kk][ty * 4 + 64];
            float4 bv0 = *(const float4*)&Bs[kk][tx * 4];
            float4 bv1 = *(const float4*)&Bs[kk][tx * 4 + 64];
            ull bp0 = pack2(bv0.x, bv0.y);
            ull bp1 = pack2(bv0.z, bv0.w);
            ull bp2 = pack2(bv1.x, bv1.y);
            ull bp3 = pack2(bv1.z, bv1.w);
            ull a;
            a = dup2(av0.x); fma2(acc[0][0], a, bp0); fma2(acc[0][1], a, bp1); fma2(acc[0][2], a, bp2); fma2(acc[0][3], a, bp3);
            a = dup2(av0.y); fma2(acc[1][0], a, bp0); fma2(acc[1][1], a, bp1); fma2(acc[1][2], a, bp2); fma2(acc[1][3], a, bp3);
            a = dup2(av0.z); fma2(acc[2][0], a, bp0); fma2(acc[2][1], a, bp1); fma2(acc[2][2], a, bp2); fma2(acc[2][3], a, bp3);
            a = dup2(av0.w); fma2(acc[3][0], a, bp0); fma2(acc[3][1], a, bp1); fma2(acc[3][2], a, bp2); fma2(acc[3][3], a, bp3);
            a = dup2(av1.x); fma2(acc[4][0], a, bp0); fma2(acc[4][1], a, bp1); fma2(acc[4][2], a, bp2); fma2(acc[4][3], a, bp3);
            a = dup2(av1.y); fma2(acc[5][0], a, bp0); fma2(acc[5][1], a, bp1); fma2(acc[5][2], a, bp2); fma2(acc[5][3], a, bp3);
            a = dup2(av1.z); fma2(acc[6][0], a, bp0); fma2(acc[6][1], a, bp1); fma2(acc[6][2], a, bp2); fma2(acc[6][3], a, bp3);
            a = dup2(av1.w); fma2(acc[7][0], a, bp0); fma2(acc[7][1], a, bp1); fma2(acc[7][2], a, bp2); fma2(acc[7][3], a, bp3);
        }
    }

    // epilogue: bias + (optional) BN affine, write float2 per n-pair
    #pragma unroll
    for (int half = 0; half < 2; half++) {
        #pragma unroll
        for (int jp = 0; jp < 2; jp++) {
            int n0 = bn0 + tx * 4 + half * 64 + jp * 2;
            float sc0 = 1.0f, sh0 = 0.0f, sc1 = 1.0f, sh1 = 0.0f;
            if (bnp) {
                float g0 = bnp[n0],     be0 = bnp[N + n0],     mm0 = bnp[2*N + n0],     vv0 = bnp[3*N + n0];
                float g1 = bnp[n0 + 1], be1 = bnp[N + n0 + 1], mm1 = bnp[2*N + n0 + 1], vv1 = bnp[3*N + n0 + 1];
                sc0 = g0 / sqrtf(vv0 + EPSF); sh0 = be0 - mm0 * sc0;
                sc1 = g1 / sqrtf(vv1 + EPSF); sh1 = be1 - mm1 * sc1;
            }
            float bs0 = bias[n0], bs1 = bias[n0 + 1];
            #pragma unroll
            for (int i = 0; i < 8; i++) {
                int m = bm0 + ty * 4 + ((i < 4) ? i : (64 + i - 4));
                float2 v = unpack2(acc[i][half * 2 + jp]);
                float2 o;
                o.x = (v.x + bs0) * sc0 + sh0;
                o.y = (v.y + bs1) * sc1 + sh1;
                *(float2*)&Out[(size_t)m * N + n0] = o;
            }
        }
    }
}

// ---------------- LIF scan (optionally fused BN affine and elementwise multiply) --
__global__ void __launch_bounds__(256) lif_kernel(
    const float* __restrict__ X, int ldx,
    const float* __restrict__ Mul, int ldm,
    const float* __restrict__ bnp,
    float* __restrict__ S)
{
    int j = blockIdx.x * blockDim.x + threadIdx.x;
    if (j >= B_DIM * C_DIM) return;
    int b = j / C_DIM, c = j % C_DIM;

    float sc = 1.0f, sh = 0.0f;
    if (bnp) {
        float g = bnp[c], be = bnp[C_DIM + c], mm = bnp[2 * C_DIM + c], vv = bnp[3 * C_DIM + c];
        sc = g / sqrtf(vv + EPSF);
        sh = be - mm * sc;
    }

    const float* xp = X + (size_t)b * ldx + c;
    const float* mp = Mul ? (Mul + (size_t)b * ldm + c) : nullptr;
    float* sp = S + (size_t)j;
    size_t stx = (size_t)B_DIM * ldx;
    size_t stm = (size_t)B_DIM * ldm;
    size_t sts = (size_t)B_DIM * C_DIM;

    float vm = 0.0f;
    for (int t = 0; t < T_DIM; t++) {
        float xv = xp[(size_t)t * stx];
        if (mp) xv *= mp[(size_t)t * stm];
        xv = xv * sc + sh;
        vm = vm * 0.5f + xv;
        float s = (vm >= 1.0f) ? 1.0f : 0.0f;
        vm = (s > 0.0f) ? 0.0f : vm;
        sp[(size_t)t * sts] = s;
    }
}

// ---------------- depthwise conv over time (K=31, SAME zero pad) ----------------
__global__ void __launch_bounds__(256) dw_kernel(
    const float* __restrict__ S1, const float* __restrict__ w,
    const float* __restrict__ bvec, float* __restrict__ Dout)
{
    __shared__ float sx[T_DIM][64];
    int b  = blockIdx.x;
    int c0 = blockIdx.y * 64;
    int tid = threadIdx.x;

    for (int i = tid; i < T_DIM * 64; i += 256) {
        int t = i >> 6, ci = i & 63;
        sx[t][ci] = S1[((size_t)t * B_DIM + b) * C_DIM + c0 + ci];
    }
    __syncthreads();

    int ci = tid & 63;
    int tg = tid >> 6;
    int c  = c0 + ci;

    float wr[K_DW];
    #pragma unroll
    for (int k = 0; k < K_DW; k++) wr[k] = w[c * K_DW + k];
    float bb = bvec[c];

    for (int t = tg * 32; t < tg * 32 + 32; t++) {
        float acc = bb;
        #pragma unroll
        for (int k = 0; k < K_DW; k++) {
            int tt = t + k - 15;
            if (tt >= 0 && tt < T_DIM) acc += sx[tt][ci] * wr[k];
        }
        Dout[((size_t)t * B_DIM + b) * C_DIM + c] = acc;
    }
}

// ---------------- launch ----------------
extern "C" void kernel_launch(void* const* d_in, const int* in_sizes, int n_in,
                              void* d_out, int out_size)
{
    const float* x        = (const float*)d_in[0];
    const float* ln_g     = (const float*)d_in[1];
    const float* ln_b     = (const float*)d_in[2];
    const float* pw1_w    = (const float*)d_in[3];
    const float* pw1_b    = (const float*)d_in[4];
    const float* bn1_p    = (const float*)d_in[5];
    const float* dw_w     = (const float*)d_in[6];
    const float* dw_b     = (const float*)d_in[7];
    const float* bn2_p    = (const float*)d_in[8];
    const float* pw2_w    = (const float*)d_in[9];
    const float* pw2_b    = (const float*)d_in[10];
    const float* bn3_p    = (const float*)d_in[11];
    const float* gsu_w    = (const float*)d_in[12];
    const float* gsu_b    = (const float*)d_in[13];
    const float* gsu_bn_p = (const float*)d_in[14];

    float *H, *Y1, *S1, *D, *S2, *Y2, *Sg, *Y3, *Sg2;
    cudaGetSymbolAddress((void**)&H,   g_H);
    cudaGetSymbolAddress((void**)&Y1,  g_Y1);
    cudaGetSymbolAddress((void**)&S1,  g_S1);
    cudaGetSymbolAddress((void**)&D,   g_D);
    cudaGetSymbolAddress((void**)&S2,  g_S2);
    cudaGetSymbolAddress((void**)&Y2,  g_Y2);
    cudaGetSymbolAddress((void**)&Sg,  g_Sg);
    cudaGetSymbolAddress((void**)&Y3,  g_Y3);
    cudaGetSymbolAddress((void**)&Sg2, g_Sg2);

    const int lif_blocks = (B_DIM * C_DIM + 255) / 256;   // 192

    // 1) LayerNorm
    ln_kernel<<<M_DIM, 256>>>(x, ln_g, ln_b, H);

    // 2) pw1 + bias + bn1
    gemm_bias_bn<<<dim3(C_DIM / BN, M_DIM / BM), 256>>>(
        H, pw1_w, pw1_b, bn1_p, Y1, M_DIM, C_DIM, C_DIM);

    // 3) LIF -> S1
    lif_kernel<<<lif_blocks, 256>>>(Y1, C_DIM, nullptr, 0, nullptr, S1);

    // 4) depthwise over time
    dw_kernel<<<dim3(B_DIM, C_DIM / 64), 256>>>(S1, dw_w, dw_b, D);

    // 5) BN2 + LIF -> S2
    lif_kernel<<<lif_blocks, 256>>>(D, C_DIM, nullptr, 0, bn2_p, S2);

    // 6) pw2 + bias + bn3 -> [out | gate]
    gemm_bias_bn<<<dim3(2 * C_DIM / BN, M_DIM / BM), 256>>>(
        S2, pw2_w, pw2_b, bn3_p, Y2, M_DIM, 2 * C_DIM, C_DIM);

    // 7) LIF(gate half) -> Sg
    lif_kernel<<<lif_blocks, 256>>>(Y2 + C_DIM, 2 * C_DIM, nullptr, 0, nullptr, Sg);

    // 8) gsu GEMM + bias + gsu_bn
    gemm_bias_bn<<<dim3(C_DIM / BN, M_DIM / BM), 256>>>(
        Sg, gsu_w, gsu_b, gsu_bn_p, Y3, M_DIM, C_DIM, C_DIM);

    // 9) LIF -> Sg2
    lif_kernel<<<lif_blocks, 256>>>(Y3, C_DIM, nullptr, 0, nullptr, Sg2);

    // 10) final LIF on out*Sg2 -> d_out
    lif_kernel<<<lif_blocks, 256>>>(Y2, 2 * C_DIM, Sg2, C_DIM, nullptr, (float*)d_out);
}